// round 13
// baseline (speedup 1.0000x reference)
#include <cuda_runtime.h>
#include <cuda_fp16.h>
#include <cstdint>

// Problem dims
#define B   64
#define NN  2048
#define NC  32
#define IC  16
#define OC  32
#define KO  (NC * OC)      // 1024
#define NCHUNK 32          // blocks per batch for k_iter (128-thr blocks)
#define NPB (NN / NCHUNK)  // 64 nodes per block -> 16 rounds per warp
#define ROUNDS (NPB / 4)   // 16

// ---------------- scratch (device globals; no runtime allocation) ----------
__device__ __half g_priors[(size_t)B * NN * KO];   // 268 MB fp16 priors [b][n][k][o]
__device__ float  g_logits[(size_t)B * NN * NC];   // 16 MB  logits  [b][n][k]
__device__ float  g_s[B * KO];                     // s accumulator (zeroed by squash)
__device__ float  g_out[B * KO];                   // current outputs v_i

// ---------------- pass 0: priors = einsum('bni,nkio->bnko'), fp16 store ----
// One block per node n. W[n] (32x16x32 fp32 = 64KB) lives in registers,
// reused across all 64 batches. Packed f32x2 FMA doubles fp32 throughput.
__global__ void __launch_bounds__(256) k_priors(const float* __restrict__ x,
                                                const float* __restrict__ w) {
    const int n  = blockIdx.x;
    const int t  = threadIdx.x;
    const int k  = t >> 3;            // capsule 0..31
    const int og = (t & 7) * 4;       // out-channel group (4 consecutive o)

    // x packed as (v,v) f32x2 per element for broadcast FMA
    __shared__ unsigned long long sx[B][IC];   // 8 KB

    for (int idx = t; idx < B * IC; idx += 256) {
        int b = idx >> 4, i = idx & 15;
        float v = x[((size_t)b * NN + n) * IC + i];
        unsigned long long pv;
        asm("mov.b64 %0, {%1, %2};" : "=l"(pv) : "f"(v), "f"(v));
        sx[b][i] = pv;
    }

    // Load this thread's W slice: W[n][k][0..15][og..og+3] -> 32 packed pairs
    unsigned long long wp[2 * IC];
    const float* wbase = w + (((size_t)n * NC + k) * IC) * OC + og;
#pragma unroll
    for (int i = 0; i < IC; i++) {
        ulonglong2 v = *(const ulonglong2*)(wbase + (size_t)i * OC);
        wp[2 * i]     = v.x;   // (w[og],   w[og+1])
        wp[2 * i + 1] = v.y;   // (w[og+2], w[og+3])
    }
    __syncthreads();

    __half* pout = g_priors + (size_t)n * KO + (size_t)k * OC + og;
#pragma unroll 1
    for (int b = 0; b < B; b++) {
        unsigned long long a0 = 0ull, a1 = 0ull;
#pragma unroll
        for (int i = 0; i < IC; i++) {
            unsigned long long xv = sx[b][i];
            asm("fma.rn.f32x2 %0, %1, %2, %0;" : "+l"(a0) : "l"(xv), "l"(wp[2 * i]));
            asm("fma.rn.f32x2 %0, %1, %2, %0;" : "+l"(a1) : "l"(xv), "l"(wp[2 * i + 1]));
        }
        float f0, f1, f2, f3;
        asm("mov.b64 {%0, %1}, %2;" : "=f"(f0), "=f"(f1) : "l"(a0));
        asm("mov.b64 {%0, %1}, %2;" : "=f"(f2), "=f"(f3) : "l"(a1));
        __half2 h01 = __floats2half2_rn(f0, f1);
        __half2 h23 = __floats2half2_rn(f2, f3);
        uint2 st;
        st.x = *(const unsigned int*)&h01;
        st.y = *(const unsigned int*)&h23;
        *(uint2*)(pout + (size_t)b * NN * KO) = st;
    }
}

// ---------------- routing pass (fused delta + softmax + weighted sum) ------
// Grid: (NCHUNK, B), 128-thread CTAs, 4 CTAs/SM = 16 warps.
// CONTIGUOUS warp loads: the 2KB node row is fetched as 4x 512B LDG.128
// (consecutive lanes -> consecutive 16B), so each LDG touches 4 cache lines
// instead of 16 -> 4x fewer L1tex wavefronts (the measured binder: L1% ~55-65
// while DRAM% plateaued at ~58 regardless of in-flight depth).
// Data mapping per lane l, chunk j: k = j*8 + (l>>2), o in [8*(l&3), +8).
// delta[k]: per-j 8-wide HFMA2 partial + 2-shuffle reduce over the 4-lane
// o-group; softmax: per-lane 4 exps + 3-shuffle group-tree. Each (k,o) is
// uniquely owned by one lane -> s-accumulation stays lane-local (acc[4][8]).
// Depth-2 via the R12 fully-unrolled 3-buffer rotation (no register copies).
// ITER==0 walks nodes in REVERSE (tail of k_priors' stream still in L2).
template <int ITER>
__global__ void __launch_bounds__(128, 4) k_iter() {
    const int b    = blockIdx.y;
    const int warp = threadIdx.x >> 5;     // 0..3
    const int lane = threadIdx.x & 31;
    const int m    = lane >> 2;            // k-subindex 0..7
    const int c    = lane & 3;             // o-slice 0..3

    __shared__ float   s_s[NC * 33];       // padded: bank-conflict-free
    __shared__ __half2 s_outh[NC][17];     // out row as half2 pairs, padded

    for (int idx = threadIdx.x; idx < NC * 33; idx += 128) s_s[idx] = 0.f;
    if (ITER > 0) {
        const float2* op = (const float2*)g_out + b * (KO / 2);
        for (int idx = threadIdx.x; idx < KO / 2; idx += 128) {
            int k = idx >> 4, r = idx & 15;
            s_outh[k][r] = __float22half2_rn(op[idx]);
        }
    }
    __syncthreads();

    float acc[4][8];
#pragma unroll
    for (int j = 0; j < 4; j++)
#pragma unroll
        for (int e = 0; e < 8; e++) acc[j][e] = 0.f;

    const int n0 = blockIdx.x * NPB;
    const __half* nodebase = g_priors + ((size_t)b * NN + n0) * KO;
    const float*  lbase    = g_logits + ((size_t)b * NN + n0) * NC;

    // address-only node remap: ITER 0 consumes nodes in reverse order
#define IDX(v) ((ITER == 0) ? (NPB - 1 - (v)) : (v))

    uint4 ub[3][4];                        // 3 rotating 64B-per-lane buffers
    float lgb[3];
    lgb[0] = lgb[1] = lgb[2] = 0.f;

    // prologue: issue loads for rounds 0 and 1
#pragma unroll
    for (int s = 0; s < 2; s++) {
        const int node = warp + 4 * s;
        const uint4* rp = (const uint4*)(nodebase + (size_t)IDX(node) * KO);
#pragma unroll
        for (int j = 0; j < 4; j++) ub[s][j] = rp[j * 32 + lane];
        if (ITER == 2) lgb[s] = lbase[(size_t)IDX(node) * NC + lane];
    }

#pragma unroll
    for (int r = 0; r < ROUNDS; r++) {
        const int nn = warp + 4 * r;

        // ---- issue load for round r+2 into buffer (r+2)%3 (static idx) ----
        if (r + 2 < ROUNDS) {
            const int pnode = warp + 4 * (r + 2);
            const uint4* rp = (const uint4*)(nodebase + (size_t)IDX(pnode) * KO);
#pragma unroll
            for (int j = 0; j < 4; j++) ub[(r + 2) % 3][j] = rp[j * 32 + lane];
            if (ITER == 2) lgb[(r + 2) % 3] = lbase[(size_t)IDX(pnode) * NC + lane];
        }

        // ---- compute on round r from buffer r%3 ----
        const __half2* ph = (const __half2*)ub[r % 3];   // chunk j = ph[4j..4j+3]

        if (ITER == 0) {
            const float pr = 1.0f / NC;
#pragma unroll
            for (int j = 0; j < 4; j++)
#pragma unroll
                for (int q = 0; q < 4; q++) {
                    float2 pf = __half22float2(ph[4 * j + q]);
                    acc[j][2 * q]     = fmaf(pr, pf.x, acc[j][2 * q]);
                    acc[j][2 * q + 1] = fmaf(pr, pf.y, acc[j][2 * q + 1]);
                }
        } else {
            // per-j partial delta over this lane's 8 o-values (fp16x2 chains)
            float dpar[4];
#pragma unroll
            for (int j = 0; j < 4; j++) {
                __half2 dh = __float2half2_rn(0.f);
#pragma unroll
                for (int q = 0; q < 4; q++)
                    dh = __hfma2(ph[4 * j + q], s_outh[j * 8 + m][4 * c + q], dh);
                float2 f = __half22float2(dh);
                dpar[j] = f.x + f.y;
            }
            // reduce over the 4-lane o-group (c dimension)
#pragma unroll
            for (int j = 0; j < 4; j++) {
                dpar[j] += __shfl_xor_sync(0xffffffffu, dpar[j], 1);
                dpar[j] += __shfl_xor_sync(0xffffffffu, dpar[j], 2);
            }

            if (ITER == 1 && c == 0) {
                float* lp = g_logits + ((size_t)b * NN + n0 + nn) * NC + m;
#pragma unroll
                for (int j = 0; j < 4; j++) lp[j * 8] = dpar[j];
            }

            float e[4], S = 0.f;
#pragma unroll
            for (int j = 0; j < 4; j++) {
                float logit = dpar[j];
                if (ITER == 2)
                    logit += __shfl_sync(0xffffffffu, lgb[r % 3], j * 8 + m);
                e[j] = __expf(logit);
                S += e[j];
            }
            // tree-sum over the 8 k-groups
            S += __shfl_xor_sync(0xffffffffu, S, 4);
            S += __shfl_xor_sync(0xffffffffu, S, 8);
            S += __shfl_xor_sync(0xffffffffu, S, 16);
            const float inv = __fdividef(1.f, S);

#pragma unroll
            for (int j = 0; j < 4; j++) {
                const float pr = e[j] * inv;
#pragma unroll
                for (int q = 0; q < 4; q++) {
                    float2 pf = __half22float2(ph[4 * j + q]);
                    acc[j][2 * q]     = fmaf(pr, pf.x, acc[j][2 * q]);
                    acc[j][2 * q + 1] = fmaf(pr, pf.y, acc[j][2 * q + 1]);
                }
            }
        }
    }
#undef IDX

    // lane-owned (k,o) accumulators -> shared (padded rows)
#pragma unroll
    for (int j = 0; j < 4; j++)
#pragma unroll
        for (int e = 0; e < 8; e++)
            atomicAdd(&s_s[(j * 8 + m) * 33 + c * 8 + e], acc[j][e]);
    __syncthreads();

    for (int idx = threadIdx.x; idx < KO; idx += 128)
        atomicAdd(&g_s[b * KO + idx], s_s[(idx >> 5) * 33 + (idx & 31)]);
}

// ---------------- squash: v = (|s|^2/(1+|s|^2)) * s/|s| -------------------
// Grid: (NC, B), 32 threads (lane = o). Also re-zeros g_s so the next pass /
// next graph replay starts clean (keeps kernel_launch deterministic).
template <bool FINAL>
__global__ void k_squash(float* __restrict__ dst) {
    const int k = blockIdx.x, b = blockIdx.y, o = threadIdx.x;
    const int idx = b * KO + k * OC + o;
    float v = g_s[idx];
    g_s[idx] = 0.f;
    float sq = v * v;
#pragma unroll
    for (int off = 16; off > 0; off >>= 1)
        sq += __shfl_xor_sync(0xffffffffu, sq, off);
    float scale = sqrtf(sq) / (1.f + sq);   // = (sq/(1+sq)) / sqrt(sq)
    float out = v * scale;
    if (FINAL) dst[idx] = out;
    else       g_out[idx] = out;
}

// ---------------- launch ----------------------------------------------------
extern "C" void kernel_launch(void* const* d_in, const int* in_sizes, int n_in,
                              void* d_out, int out_size) {
    const float* x = (const float*)d_in[0];          // [B, NN, IC]
    const float* w = (const float*)d_in[1];          // [NN, NC, IC, OC]
    float* out = (float*)d_out;                      // [B, 1, NC, OC]

    k_priors<<<NN, 256>>>(x, w);

    k_iter<0><<<dim3(NCHUNK, B), 128>>>();
    k_squash<false><<<dim3(NC, B), 32>>>(nullptr);

    k_iter<1><<<dim3(NCHUNK, B), 128>>>();
    k_squash<false><<<dim3(NC, B), 32>>>(nullptr);

    k_iter<2><<<dim3(NCHUNK, B), 128>>>();
    k_squash<true><<<dim3(NC, B), 32>>>(out);
}

// round 15
// speedup vs baseline: 1.0290x; 1.0290x over previous
#include <cuda_runtime.h>
#include <cuda_fp16.h>
#include <cstdint>

// Problem dims
#define B   64
#define NN  2048
#define NC  32
#define IC  16
#define OC  32
#define KO  (NC * OC)        // 1024
#define NCHUNK 64            // CTAs per batch for k_iter
#define NPB (NN / NCHUNK)    // 32 nodes per CTA
#define SNODES 4             // nodes per stage (1 per warp)
#define NSTAGES (NPB / SNODES) // 8 stages
#define STAGE_B (SNODES * KO * 2) // 8192 bytes per stage

// ---------------- scratch (device globals; no runtime allocation) ----------
__device__ __half g_priors[(size_t)B * NN * KO];   // 268 MB fp16 priors [b][n][k][o]
__device__ float  g_logits[(size_t)B * NN * NC];   // 16 MB  logits  [b][n][k]
__device__ float  g_s[B * KO];                     // s accumulator (zeroed by squash)
__device__ float  g_out[B * KO];                   // current outputs v_i

// ---------------- PTX helpers ----------------------------------------------
__device__ __forceinline__ uint32_t s2u(const void* p) {
    return (uint32_t)__cvta_generic_to_shared(p);
}
__device__ __forceinline__ void mb_init(uint32_t a, uint32_t cnt) {
    asm volatile("mbarrier.init.shared.b64 [%0], %1;" :: "r"(a), "r"(cnt) : "memory");
}
__device__ __forceinline__ void mb_expect(uint32_t a, uint32_t bytes) {
    asm volatile("mbarrier.arrive.expect_tx.shared.b64 _, [%0], %1;"
                 :: "r"(a), "r"(bytes) : "memory");
}
__device__ __forceinline__ void mb_arrive(uint32_t a) {
    asm volatile("mbarrier.arrive.shared.b64 _, [%0];" :: "r"(a) : "memory");
}
__device__ __forceinline__ void mb_wait(uint32_t a, uint32_t parity) {
    asm volatile(
        "{\n\t.reg .pred P;\n"
        "W%=:\n\t"
        "mbarrier.try_wait.parity.acquire.cta.shared::cta.b64 P, [%0], %1, 0x989680;\n\t"
        "@P bra D%=;\n\t"
        "bra W%=;\n"
        "D%=:\n\t}"
        :: "r"(a), "r"(parity) : "memory");
}
__device__ __forceinline__ void bulk_g2s(uint32_t dst_s, const void* src_g,
                                         uint32_t bytes, uint32_t mbar_s) {
    asm volatile(
        "cp.async.bulk.shared::cta.global.mbarrier::complete_tx::bytes "
        "[%0], [%1], %2, [%3];"
        :: "r"(dst_s), "l"(src_g), "r"(bytes), "r"(mbar_s) : "memory");
}

// ---------------- pass 0: priors = einsum('bni,nkio->bnko'), fp16 store ----
// One block per node n. W[n] (32x16x32 fp32 = 64KB) lives in registers,
// reused across all 64 batches. Packed f32x2 FMA doubles fp32 throughput.
__global__ void __launch_bounds__(256) k_priors(const float* __restrict__ x,
                                                const float* __restrict__ w) {
    const int n  = blockIdx.x;
    const int t  = threadIdx.x;
    const int k  = t >> 3;            // capsule 0..31
    const int og = (t & 7) * 4;       // out-channel group (4 consecutive o)

    __shared__ unsigned long long sx[B][IC];   // x packed (v,v) f32x2

    for (int idx = t; idx < B * IC; idx += 256) {
        int b = idx >> 4, i = idx & 15;
        float v = x[((size_t)b * NN + n) * IC + i];
        unsigned long long pv;
        asm("mov.b64 %0, {%1, %2};" : "=l"(pv) : "f"(v), "f"(v));
        sx[b][i] = pv;
    }

    unsigned long long wp[2 * IC];
    const float* wbase = w + (((size_t)n * NC + k) * IC) * OC + og;
#pragma unroll
    for (int i = 0; i < IC; i++) {
        ulonglong2 v = *(const ulonglong2*)(wbase + (size_t)i * OC);
        wp[2 * i]     = v.x;
        wp[2 * i + 1] = v.y;
    }
    __syncthreads();

    __half* pout = g_priors + (size_t)n * KO + (size_t)k * OC + og;
#pragma unroll 1
    for (int b = 0; b < B; b++) {
        unsigned long long a0 = 0ull, a1 = 0ull;
#pragma unroll
        for (int i = 0; i < IC; i++) {
            unsigned long long xv = sx[b][i];
            asm("fma.rn.f32x2 %0, %1, %2, %0;" : "+l"(a0) : "l"(xv), "l"(wp[2 * i]));
            asm("fma.rn.f32x2 %0, %1, %2, %0;" : "+l"(a1) : "l"(xv), "l"(wp[2 * i + 1]));
        }
        float f0, f1, f2, f3;
        asm("mov.b64 {%0, %1}, %2;" : "=f"(f0), "=f"(f1) : "l"(a0));
        asm("mov.b64 {%0, %1}, %2;" : "=f"(f2), "=f"(f3) : "l"(a1));
        __half2 h01 = __floats2half2_rn(f0, f1);
        __half2 h23 = __floats2half2_rn(f2, f3);
        uint2 st;
        st.x = *(const unsigned int*)&h01;
        st.y = *(const unsigned int*)&h23;
        *(uint2*)(pout + (size_t)b * NN * KO) = st;
    }
}

// ---------------- routing pass: TMA bulk producer / warp consumers ---------
// Grid: (NCHUNK, B), 128-thr CTAs, 6 CTAs/SM (static smem ~35KB).
// tid0 streams priors via cp.async.bulk (UBLKCP, 8KB/request) into a 3-slot
// smem ring; the 4 warps each consume one 2KB node per stage from smem.
// This removes the per-SM outstanding-LDG request cap that pinned DRAM% at
// ~56-58% across R3/R10/R12/R13: in-flight bytes now live in the TMA engine.
// Consumer math = R13 coalesced mapping: lane (m=l>>2, c=l&3); chunk j holds
// k=j*8+m, o in [8c, 8c+8). delta via HFMA2 + 2 shuffles; softmax via 4 exps
// + 3-shuffle tree; (k,o) uniquely lane-owned -> fp32 acc stays in registers.
// ITER==0: uniform probs, stages consumed in REVERSE (L2 tail of k_priors).
// ITER==1: logits = delta (stored). ITER==2: logits = stored + delta, with
// the 4KB stored-logit block bulk-loaded once at kernel start.
template <int ITER>
__global__ void __launch_bounds__(128, 6) k_iter() {
    __shared__ __align__(128) char sbuf[3][STAGE_B];       // 24KB ring
    __shared__ float   s_s[NC * 33];                       // padded partials
    __shared__ __half2 s_outh[NC][17];                     // out rows (half2)
    __shared__ float   s_lg[NPB * NC];                     // 4KB logits (ITER2)
    __shared__ __align__(8) unsigned long long barmem[7];  // full[3],empty[3],lg

    const int tid  = threadIdx.x;
    const int b    = blockIdx.y;
    const int w    = tid >> 5;             // warp 0..3
    const int lane = tid & 31;
    const int m    = lane >> 2;            // k-subindex 0..7
    const int c    = lane & 3;             // o-slice 0..3

    const uint32_t fullb  = s2u(&barmem[0]);   // +8*i
    const uint32_t emptyb = s2u(&barmem[3]);
    const uint32_t lgbar  = s2u(&barmem[6]);

    if (tid == 0) {
#pragma unroll
        for (int i = 0; i < 3; i++) {
            mb_init(fullb + 8 * i, 1);     // completed by TMA tx bytes
            mb_init(emptyb + 8 * i, 4);    // one arrive per warp
        }
        mb_init(lgbar, 1);
    }

    for (int idx = tid; idx < NC * 33; idx += 128) s_s[idx] = 0.f;
    if (ITER > 0) {
        const float2* op = (const float2*)g_out + b * (KO / 2);
        for (int idx = tid; idx < KO / 2; idx += 128) {
            int k = idx >> 4, r = idx & 15;
            s_outh[k][r] = __float22half2_rn(op[idx]);
        }
    }
    __syncthreads();                       // barriers inited, s_outh ready

    const int n0 = blockIdx.x * NPB;
    const __half* pbase = g_priors + ((size_t)b * NN + n0) * KO;

    // chunk order: ITER0 consumes stages in reverse node order
#define CH(s) ((ITER == 0) ? (NSTAGES - 1 - (s)) : (s))

    if (tid == 0) {
        if (ITER == 2) {
            mb_expect(lgbar, NPB * NC * 4);
            bulk_g2s(s2u(s_lg), g_logits + ((size_t)b * NN + n0) * NC,
                     NPB * NC * 4, lgbar);
        }
#pragma unroll
        for (int s = 0; s < 3; s++) {      // prologue: fill slots 0..2
            mb_expect(fullb + 8 * s, STAGE_B);
            bulk_g2s(s2u(sbuf[s]), pbase + (size_t)CH(s) * SNODES * KO,
                     STAGE_B, fullb + 8 * s);
        }
    }
    if (ITER == 2) mb_wait(lgbar, 0);

    float acc[4][8];
#pragma unroll
    for (int j = 0; j < 4; j++)
#pragma unroll
        for (int e = 0; e < 8; e++) acc[j][e] = 0.f;

#pragma unroll 1
    for (int s = 0; s < NSTAGES; s++) {
        const int slot = s % 3;
        mb_wait(fullb + 8 * slot, (uint32_t)((s / 3) & 1));

        const int chunk = CH(s);
        const int node  = chunk * SNODES + w;          // node index in CTA
        const char* nb  = sbuf[slot] + w * (KO * 2);   // my 2KB node row

        if (ITER == 0) {
            const float pr = 1.0f / NC;
#pragma unroll
            for (int j = 0; j < 4; j++) {
                uint4 u = *(const uint4*)(nb + j * 512 + lane * 16);
                const __half2* hp = (const __half2*)&u;
#pragma unroll
                for (int q = 0; q < 4; q++) {
                    float2 pf = __half22float2(hp[q]);
                    acc[j][2 * q]     = fmaf(pr, pf.x, acc[j][2 * q]);
                    acc[j][2 * q + 1] = fmaf(pr, pf.y, acc[j][2 * q + 1]);
                }
            }
        } else {
            uint4 uj[4];
#pragma unroll
            for (int j = 0; j < 4; j++)
                uj[j] = *(const uint4*)(nb + j * 512 + lane * 16);

            float dpar[4];
#pragma unroll
            for (int j = 0; j < 4; j++) {
                const __half2* hp = (const __half2*)&uj[j];
                __half2 dh = __float2half2_rn(0.f);
#pragma unroll
                for (int q = 0; q < 4; q++)
                    dh = __hfma2(hp[q], s_outh[j * 8 + m][4 * c + q], dh);
                float2 f = __half22float2(dh);
                dpar[j] = f.x + f.y;
            }
#pragma unroll
            for (int j = 0; j < 4; j++) {
                dpar[j] += __shfl_xor_sync(0xffffffffu, dpar[j], 1);
                dpar[j] += __shfl_xor_sync(0xffffffffu, dpar[j], 2);
            }

            if (ITER == 1 && c == 0) {
                float* lp = g_logits + ((size_t)b * NN + n0 + node) * NC + m;
#pragma unroll
                for (int j = 0; j < 4; j++) lp[j * 8] = dpar[j];
            }

            float e[4], S = 0.f;
#pragma unroll
            for (int j = 0; j < 4; j++) {
                float logit = dpar[j];
                if (ITER == 2) logit += s_lg[node * NC + j * 8 + m];
                e[j] = __expf(logit);
                S += e[j];
            }
            S += __shfl_xor_sync(0xffffffffu, S, 4);
            S += __shfl_xor_sync(0xffffffffu, S, 8);
            S += __shfl_xor_sync(0xffffffffu, S, 16);
            const float inv = __fdividef(1.f, S);

#pragma unroll
            for (int j = 0; j < 4; j++) {
                const float pr = e[j] * inv;
                const __half2* hp = (const __half2*)&uj[j];
#pragma unroll
                for (int q = 0; q < 4; q++) {
                    float2 pf = __half22float2(hp[q]);
                    acc[j][2 * q]     = fmaf(pr, pf.x, acc[j][2 * q]);
                    acc[j][2 * q + 1] = fmaf(pr, pf.y, acc[j][2 * q + 1]);
                }
            }
        }

        __syncwarp();
        if (lane == 0) mb_arrive(emptyb + 8 * slot);

        // producer: refill this slot for stage s+3 once all warps released it
        if (tid == 0 && s + 3 < NSTAGES) {
            mb_wait(emptyb + 8 * slot, (uint32_t)((s / 3) & 1));
            mb_expect(fullb + 8 * slot, STAGE_B);
            bulk_g2s(s2u(sbuf[slot]), pbase + (size_t)CH(s + 3) * SNODES * KO,
                     STAGE_B, fullb + 8 * slot);
        }
    }
#undef CH

    // lane-owned (k,o) accumulators -> shared (padded rows)
#pragma unroll
    for (int j = 0; j < 4; j++)
#pragma unroll
        for (int e = 0; e < 8; e++)
            atomicAdd(&s_s[(j * 8 + m) * 33 + c * 8 + e], acc[j][e]);
    __syncthreads();

    for (int idx = tid; idx < KO; idx += 128)
        atomicAdd(&g_s[b * KO + idx], s_s[(idx >> 5) * 33 + (idx & 31)]);
}

// ---------------- squash: v = (|s|^2/(1+|s|^2)) * s/|s| -------------------
// Grid: (NC, B), 32 threads (lane = o). Also re-zeros g_s so the next pass /
// next graph replay starts clean (keeps kernel_launch deterministic).
template <bool FINAL>
__global__ void k_squash(float* __restrict__ dst) {
    const int k = blockIdx.x, b = blockIdx.y, o = threadIdx.x;
    const int idx = b * KO + k * OC + o;
    float v = g_s[idx];
    g_s[idx] = 0.f;
    float sq = v * v;
#pragma unroll
    for (int off = 16; off > 0; off >>= 1)
        sq += __shfl_xor_sync(0xffffffffu, sq, off);
    float scale = sqrtf(sq) / (1.f + sq);   // = (sq/(1+sq)) / sqrt(sq)
    float out = v * scale;
    if (FINAL) dst[idx] = out;
    else       g_out[idx] = out;
}

// ---------------- launch ----------------------------------------------------
extern "C" void kernel_launch(void* const* d_in, const int* in_sizes, int n_in,
                              void* d_out, int out_size) {
    const float* x = (const float*)d_in[0];          // [B, NN, IC]
    const float* w = (const float*)d_in[1];          // [NN, NC, IC, OC]
    float* out = (float*)d_out;                      // [B, 1, NC, OC]

    // Max shared-memory carveout so 6 CTAs/SM (6 x ~35KB) can co-reside.
    // Host-side attribute sets: capture-safe, idempotent (R7 precedent).
    cudaFuncSetAttribute(k_iter<0>, cudaFuncAttributePreferredSharedMemoryCarveout, 100);
    cudaFuncSetAttribute(k_iter<1>, cudaFuncAttributePreferredSharedMemoryCarveout, 100);
    cudaFuncSetAttribute(k_iter<2>, cudaFuncAttributePreferredSharedMemoryCarveout, 100);

    k_priors<<<NN, 256>>>(x, w);

    k_iter<0><<<dim3(NCHUNK, B), 128>>>();
    k_squash<false><<<dim3(NC, B), 32>>>(nullptr);

    k_iter<1><<<dim3(NCHUNK, B), 128>>>();
    k_squash<false><<<dim3(NC, B), 32>>>(nullptr);

    k_iter<2><<<dim3(NCHUNK, B), 128>>>();
    k_squash<true><<<dim3(NC, B), 32>>>(out);
}